// round 13
// baseline (speedup 1.0000x reference)
#include <cuda_runtime.h>
#include <cstdint>

#define NT 16384
#define ND 4096
#define NE 64
#define BM 128
#define KC 64
#define NCH 32              // chunks per CTA (split-K of 2)
#define NTB 128             // token blocks
#define NTHREADS 256
#define TAU 5e-4f
#define CTAFIX 128

// ---------------- global scratch (no cudaMalloc; zero-initialized at load,
// re-zeroed in-kernel each call -> deterministic across graph replays)
__device__ float g_sumP[NE];
__device__ float g_cnt[NE];
__device__ int   g_done;
__device__ int   g_tick[NTB];
__device__ float g_part[(size_t)NTB * BM * NE];   // 4 MB split-K partials

// ---------------- smem layout: two chunk buffers, each 55296 B ----------------
#define XROWB 144
#define XH_OFF 0              // X hi  [128 tokens][64 k]  18432 B
#define XL_OFF 18432          // X lo
#define WH_OFF 36864          // W hi  [64 experts][64 k]   9216 B
#define WL_OFF 46080          // W lo
#define BUF_BYTES 55296
#define SMEM_BYTES (2 * BUF_BYTES)
#define LSTR 132              // logits [64 experts][128 tokens] pitch (words)

__device__ __forceinline__ uint32_t smem_u32(const void* p) {
    uint32_t a;
    asm("{ .reg .u64 t; cvta.to.shared.u64 t, %1; cvt.u32.u64 %0, t; }" : "=r"(a) : "l"(p));
    return a;
}

#define LDSM4(r, addr) \
    asm volatile("ldmatrix.sync.aligned.m8n8.x4.shared.b16 {%0,%1,%2,%3}, [%4];" \
        : "=r"((r)[0]), "=r"((r)[1]), "=r"((r)[2]), "=r"((r)[3]) : "r"(addr))

#define MMA16816(d, a, b0, b1) \
    asm volatile("mma.sync.aligned.m16n8k16.row.col.f32.bf16.bf16.f32 " \
        "{%0,%1,%2,%3},{%4,%5,%6,%7},{%8,%9},{%0,%1,%2,%3};" \
        : "+f"((d)[0]), "+f"((d)[1]), "+f"((d)[2]), "+f"((d)[3]) \
        : "r"((a)[0]), "r"((a)[1]), "r"((a)[2]), "r"((a)[3]), "r"(b0), "r"(b1))

// one split-product term: 8 MMAs, each acc tile touched once (reuse distance 8)
#define MMA_TERM(A0, A1, B0, B1) \
    MMA16816(acc[0][0], A0, (B0)[0], (B0)[1]); \
    MMA16816(acc[0][1], A0, (B0)[2], (B0)[3]); \
    MMA16816(acc[0][2], A0, (B1)[0], (B1)[1]); \
    MMA16816(acc[0][3], A0, (B1)[2], (B1)[3]); \
    MMA16816(acc[1][0], A1, (B0)[0], (B0)[1]); \
    MMA16816(acc[1][1], A1, (B0)[2], (B0)[3]); \
    MMA16816(acc[1][2], A1, (B1)[0], (B1)[1]); \
    MMA16816(acc[1][3], A1, (B1)[2], (B1)[3]);

// Compensated fp32 accumulate: two-prod (FMA) + two-sum, all on the FFMA pipe.
__device__ __forceinline__ void comp_fma(float a, float b, float& s, float& c) {
    float p = a * b;
    float e = fmaf(a, b, -p);
    float t = s + p;
    float bp = t - s;
    float err = (s - (t - bp)) + (p - bp);
    s = t;
    c += err + e;
}

// Exact dot X[tok] . W[e] per warp (compensated fp32, 4 ILP chains, full K).
__device__ __forceinline__ double warp_exact_dot(
    const float* __restrict__ X, const float* __restrict__ W,
    int tok, int e, int lane) {
    const float4* xp = reinterpret_cast<const float4*>(X + (size_t)tok * ND) + lane;
    const float4* wp = reinterpret_cast<const float4*>(W + (size_t)e * ND) + lane;
    float s0 = 0.f, k0 = 0.f, s1 = 0.f, k1 = 0.f;
    float s2 = 0.f, k2 = 0.f, s3 = 0.f, k3 = 0.f;
    #pragma unroll 8
    for (int it = 0; it < 32; it++) {
        float4 a = xp[it * 32];
        float4 b = wp[it * 32];
        comp_fma(a.x, b.x, s0, k0);
        comp_fma(a.y, b.y, s1, k1);
        comp_fma(a.z, b.z, s2, k2);
        comp_fma(a.w, b.w, s3, k3);
    }
    double s = ((double)s0 + s1) + ((double)s2 + s3)
             + (((double)k0 + k1) + ((double)k2 + k3));
    #pragma unroll
    for (int o = 16; o; o >>= 1)
        s += __shfl_xor_sync(0xffffffffu, s, o);
    return s;
}

extern __shared__ char dsm[];

__global__ __launch_bounds__(NTHREADS, 2)
void router_gemm(const float* __restrict__ X, const float* __restrict__ W,
                 float* __restrict__ out) {
    __shared__ float s_max[BM];
    __shared__ float s_invZ[BM];
    __shared__ float s_cnt[NE];
    __shared__ float s_sumP[NE];
    __shared__ int   s_nfix;
    __shared__ short s_ftok[CTAFIX];
    __shared__ uint2 s_fcand[CTAFIX];
    __shared__ short s_fcnt[CTAFIX];
    __shared__ float s_ex[NE];
    __shared__ int   s_second;
    __shared__ int   s_last;

    const int tid = threadIdx.x;
    const int lane = tid & 31;
    const int wid = tid >> 5;
    const int warp_m = wid & 1;       // expert half  (32 experts)
    const int warp_n = wid >> 1;      // token quarter (32 tokens)
    const int tb = blockIdx.x & (NTB - 1);      // token block
    const int kb = blockIdx.x >> 7;             // k half
    const int mblk = tb * BM;
    const uint32_t smem = smem_u32(dsm);

    if (tid < NE) { s_cnt[tid] = 0.f; s_sumP[tid] = 0.f; }
    if (tid == 0) s_nfix = 0;

    // ---- GMEM load mapping: instr l: row = (tid>>4)+16l, f4 = tid&15 ----
    const int row0 = tid >> 4;
    const int f4i  = tid & 15;
    const float4* xg = reinterpret_cast<const float4*>(X + (size_t)(mblk + row0) * ND)
                       + f4i + (size_t)kb * 512;
    const float4* wg = reinterpret_cast<const float4*>(W + (size_t)row0 * ND)
                       + f4i + (size_t)kb * 512;

    float4 xr[8], wr[4];

#define LDGX(c) { _Pragma("unroll") for (int l = 0; l < 8; l++) \
        xr[l] = xg[(size_t)l * 16 * (ND / 4) + (c) * 16]; }
#define LDGW(c) { _Pragma("unroll") for (int l = 0; l < 4; l++) \
        wr[l] = wg[(size_t)l * 16 * (ND / 4) + (c) * 16]; }

    // split f32 -> bf16 hi (truncate) + bf16 lo (rn of residual), store both
#define CVTSTS(v, hoff, loff) { \
    uint32_t h0, h1, l0, l1; \
    asm("prmt.b32 %0, %1, %2, 0x7632;" : "=r"(h0) : "r"(__float_as_uint((v).x)), "r"(__float_as_uint((v).y))); \
    asm("prmt.b32 %0, %1, %2, 0x7632;" : "=r"(h1) : "r"(__float_as_uint((v).z)), "r"(__float_as_uint((v).w))); \
    float lx = (v).x - __uint_as_float(__float_as_uint((v).x) & 0xffff0000u); \
    float ly = (v).y - __uint_as_float(__float_as_uint((v).y) & 0xffff0000u); \
    float lz = (v).z - __uint_as_float(__float_as_uint((v).z) & 0xffff0000u); \
    float lw = (v).w - __uint_as_float(__float_as_uint((v).w) & 0xffff0000u); \
    asm("cvt.rn.bf16x2.f32 %0, %1, %2;" : "=r"(l0) : "f"(ly), "f"(lx)); \
    asm("cvt.rn.bf16x2.f32 %0, %1, %2;" : "=r"(l1) : "f"(lw), "f"(lz)); \
    *reinterpret_cast<uint2*>(dsm + (hoff)) = make_uint2(h0, h1); \
    *reinterpret_cast<uint2*>(dsm + (loff)) = make_uint2(l0, l1); }

#define STORE_CHUNK(bufoff) { \
    _Pragma("unroll") for (int l = 0; l < 8; l++) { \
        int boff = (row0 + 16 * l) * XROWB + f4i * 8; \
        CVTSTS(xr[l], (bufoff) + XH_OFF + boff, (bufoff) + XL_OFF + boff); } \
    _Pragma("unroll") for (int l = 0; l < 4; l++) { \
        int boff = (row0 + 16 * l) * XROWB + f4i * 8; \
        CVTSTS(wr[l], (bufoff) + WH_OFF + boff, (bufoff) + WL_OFF + boff); } }

    // ---- fragment addresses (ldmatrix), buffer-invariant parts ----
    uint32_t aH0, aL0, bH0, bL0;
    {
        int ar = warp_m * 32 + (lane & 15);
        int ac = (lane >> 4) * 16;
        aH0 = smem + WH_OFF + ar * XROWB + ac;
        aL0 = smem + WL_OFF + ar * XROWB + ac;
        int br = warp_n * 32 + ((lane >> 4) * 8) + (lane & 7);
        int bc = ((lane >> 3) & 1) * 16;
        bH0 = smem + XH_OFF + br * XROWB + bc;
        bL0 = smem + XL_OFF + br * XROWB + bc;
    }

    float acc[2][4][4];
    #pragma unroll
    for (int s = 0; s < 2; s++)
        #pragma unroll
        for (int j = 0; j < 4; j++)
            #pragma unroll
            for (int q = 0; q < 4; q++) acc[s][j][q] = 0.f;

#define MMA_CHUNK(cb) { \
    _Pragma("unroll") \
    for (int kk = 0; kk < 4; kk++) { \
        const uint32_t off = (cb) + kk * 32; \
        uint32_t ah0[4], ah1[4], al0[4], al1[4]; \
        uint32_t bh0[4], bh1[4], bl0[4], bl1[4]; \
        LDSM4(ah0, aH0 + off);               LDSM4(ah1, aH0 + off + 16 * XROWB); \
        LDSM4(al0, aL0 + off);               LDSM4(al1, aL0 + off + 16 * XROWB); \
        LDSM4(bh0, bH0 + off);               LDSM4(bh1, bH0 + off + 16 * XROWB); \
        LDSM4(bl0, bL0 + off);               LDSM4(bl1, bL0 + off + 16 * XROWB); \
        MMA_TERM(ah0, ah1, bh0, bh1); \
        MMA_TERM(ah0, ah1, bl0, bl1); \
        MMA_TERM(al0, al1, bh0, bh1); \
    } }

    // prologue
    LDGX(0); LDGW(0);
    STORE_CHUNK(0);
    __syncthreads();

    // mainloop: LDG placed after MMA (regs <= 128); peer CTA hides latency
    for (int c = 0; c < NCH; c++) {
        MMA_CHUNK((uint32_t)(c & 1) * BUF_BYTES);
        if (c + 1 < NCH) {
            LDGX(c + 1); LDGW(c + 1);
            STORE_CHUNK((uint32_t)((c + 1) & 1) * BUF_BYTES);
        }
        __syncthreads();
    }

    // ---- fragments -> partial logits[e][t] in smem buffer 0 ----
    float* L = reinterpret_cast<float*>(dsm);
    #pragma unroll
    for (int s = 0; s < 2; s++) {
        int er = warp_m * 32 + s * 16 + (lane >> 2);
        #pragma unroll
        for (int j = 0; j < 4; j++) {
            int tc = warp_n * 32 + j * 8 + 2 * (lane & 3);
            *reinterpret_cast<float2*>(&L[er * LSTR + tc])       = make_float2(acc[s][j][0], acc[s][j][1]);
            *reinterpret_cast<float2*>(&L[(er + 8) * LSTR + tc]) = make_float2(acc[s][j][2], acc[s][j][3]);
        }
    }
    __syncthreads();

    // ---- split-K combine: add partials to global, elect second finisher ----
    float* gp = g_part + (size_t)tb * (BM * NE);
    #pragma unroll
    for (int u = 0; u < 32; u++) {
        int i = tid * 32 + u;               // i = e*128 + t
        atomicAdd(&gp[i], L[(i >> 7) * LSTR + (i & 127)]);
    }
    __threadfence();
    if (tid == 0)
        s_second = (atomicAdd(&g_tick[tb], 1) == 1) ? 1 : 0;
    __syncthreads();

    if (s_second) {
        __threadfence();   // acquire: see peer's atomics
        // reload summed logits (L2, bypass L1) and re-zero scratch
        #pragma unroll
        for (int u = 0; u < 32; u++) {
            int i = tid * 32 + u;
            float v = __ldcg(&gp[i]);
            L[(i >> 7) * LSTR + (i & 127)] = v;
            gp[i] = 0.f;
        }
        if (tid == 0) g_tick[tb] = 0;
        __syncthreads();

        // pass 1: per-token top-2, routing softmax, candidate collection
        if (tid < BM) {
            const int t = tid;
            const float NEG = __int_as_float(0xff800000);
            float best = NEG, sec = NEG;
            int bi = 0, si = 0;
            #pragma unroll 8
            for (int e = 0; e < NE; e++) {
                float v = L[e * LSTR + t];
                if (v > best)      { sec = best; si = bi; best = v; bi = e; }
                else if (v > sec)  { sec = v; si = e; }
            }
            float Z = 0.f;
            uint32_t c0 = 0, c1 = 0;
            int cnt = 0;
            const float thresh = sec - TAU;
            #pragma unroll 8
            for (int e = 0; e < NE; e++) {
                float v = L[e * LSTR + t];
                Z += __expf(v - best);
                if (v > thresh) {
                    if (cnt < 4)      c0 |= (uint32_t)e << (8 * cnt);
                    else if (cnt < 8) c1 |= (uint32_t)e << (8 * (cnt - 4));
                    cnt++;
                }
            }

            float w0 = 1.f / (1.f + __expf(sec - best));
            float w1 = 1.f - w0;

            size_t tok = (size_t)(mblk + t);
            out[tok * 2 + 0] = w0;
            out[tok * 2 + 1] = w1;
            out[(size_t)2 * NT + tok * 2 + 0] = (float)bi;
            out[(size_t)2 * NT + tok * 2 + 1] = (float)si;

            s_max[t]  = best;
            s_invZ[t] = 1.f / Z;
            atomicAdd(&s_cnt[bi], 1.f);
            atomicAdd(&s_cnt[si], 1.f);

            if (cnt > 2 || (best - sec) < TAU) {
                int idx = atomicAdd(&s_nfix, 1);
                s_ftok[idx]  = (short)t;
                s_fcand[idx] = make_uint2(c0, c1);
                s_fcnt[idx]  = (short)cnt;
            }
        }
        __syncthreads();

        // pass 2: per-expert softmax-prob sums for aux loss
        {
            const int e = tid & 63;
            const int q = tid >> 6;
            float ssum = 0.f;
            #pragma unroll 8
            for (int t = q * 32; t < q * 32 + 32; t++)
                ssum += __expf(L[e * LSTR + t] - s_max[t]) * s_invZ[t];
            atomicAdd(&s_sumP[e], ssum);
        }
        __syncthreads();

        if (tid < NE) {
            atomicAdd(&g_sumP[tid], s_sumP[tid]);
            atomicAdd(&g_cnt[tid],  s_cnt[tid]);
        }

        // ---- inline exact fixup of this block's flagged tokens ----
        const int nfix = s_nfix;
        for (int i = 0; i < nfix; i++) {
            const int tok = mblk + (int)s_ftok[i];
            const int cnt = (int)s_fcnt[i];
            const uint2 cd = s_fcand[i];

            if (cnt <= 8) {
                if (wid < cnt) {
                    int e = (int)((wid < 4 ? (cd.x >> (8 * wid))
                                           : (cd.y >> (8 * (wid - 4)))) & 0xffu);
                    double s = warp_exact_dot(X, W, tok, e, lane);
                    if (lane == 0) s_ex[wid] = (float)s;
                }
                __syncthreads();
                if (tid == 0) {
                    float best = -1e30f, sec = -1e30f;
                    int bi = 0, si = 0;
                    for (int j = 0; j < cnt; j++) {
                        int e = (int)((j < 4 ? (cd.x >> (8 * j))
                                             : (cd.y >> (8 * (j - 4)))) & 0xffu);
                        float v = s_ex[j];
                        if (v > best)     { sec = best; si = bi; best = v; bi = e; }
                        else if (v > sec) { sec = v; si = e; }
                    }
                    float w0 = 1.f / (1.f + __expf(sec - best));
                    out[(size_t)tok * 2 + 0] = w0;
                    out[(size_t)tok * 2 + 1] = 1.f - w0;
                    out[(size_t)2 * NT + (size_t)tok * 2 + 0] = (float)bi;
                    out[(size_t)2 * NT + (size_t)tok * 2 + 1] = (float)si;
                }
                __syncthreads();
            } else {
                #pragma unroll 1
                for (int j = 0; j < 8; j++) {
                    int e = wid * 8 + j;
                    double s = warp_exact_dot(X, W, tok, e, lane);
                    if (lane == 0) s_ex[e] = (float)s;
                }
                __syncthreads();
                if (tid == 0) {
                    float best = -1e30f, sec = -1e30f;
                    int bi = 0, si = 0;
                    for (int e = 0; e < NE; e++) {
                        float v = s_ex[e];
                        if (v > best)     { sec = best; si = bi; best = v; bi = e; }
                        else if (v > sec) { sec = v; si = e; }
                    }
                    float w0 = 1.f / (1.f + __expf(sec - best));
                    out[(size_t)tok * 2 + 0] = w0;
                    out[(size_t)tok * 2 + 1] = 1.f - w0;
                    out[(size_t)2 * NT + (size_t)tok * 2 + 0] = (float)bi;
                    out[(size_t)2 * NT + (size_t)tok * 2 + 1] = (float)si;
                }
                __syncthreads();
            }
        }
    }

    // ---- last CTA to finish: aux-loss finalize + scratch re-zero ----
    __threadfence();
    if (tid == 0)
        s_last = (atomicAdd(&g_done, 1) == (int)gridDim.x - 1) ? 1 : 0;
    __syncthreads();
    if (s_last) {
        if (tid < 32) {
            float v = g_cnt[tid] * g_sumP[tid] + g_cnt[tid + 32] * g_sumP[tid + 32];
            #pragma unroll
            for (int o = 16; o; o >>= 1) v += __shfl_xor_sync(0xffffffffu, v, o);
            if (tid == 0)
                out[(size_t)4 * NT] = v * (float)NE / ((float)NT * 2.0f * (float)NT);
        }
        __syncthreads();
        if (tid < NE) { g_sumP[tid] = 0.f; g_cnt[tid] = 0.f; }
        if (tid == 0) g_done = 0;
    }
}

extern "C" void kernel_launch(void* const* d_in, const int* in_sizes, int n_in,
                              void* d_out, int out_size) {
    const float* X = (const float*)d_in[0];   // hidden_states [16384, 4096]
    const float* W = (const float*)d_in[1];   // W_gate        [64, 4096]
    float* out = (float*)d_out;

    cudaFuncSetAttribute(router_gemm, cudaFuncAttributeMaxDynamicSharedMemorySize,
                         SMEM_BYTES);

    router_gemm<<<2 * NTB, NTHREADS, SMEM_BYTES>>>(X, W, out);
}

// round 14
// speedup vs baseline: 1.7662x; 1.7662x over previous
#include <cuda_runtime.h>
#include <cstdint>

#define NT 16384
#define ND 4096
#define NE 64
#define BM 128
#define KC 64
#define NCHUNK (ND / KC)
#define NTHREADS 512
#define TAU 5e-4f
#define CTAFIX 128

// ---------------- global scratch (no cudaMalloc; zero-initialized at load,
// re-zeroed by the last CTA each call -> deterministic across graph replays)
__device__ float g_sumP[NE];
__device__ float g_cnt[NE];
__device__ int   g_done;

// ---------------- smem layout: two chunk buffers, each 55296 B ----------------
// bf16 tiles, row pitch 144 B (64 bf16 = 128 B + 16 B pad -> conflict-free LDSM)
#define XROWB 144
#define XH_OFF 0              // X hi  [128 tokens][64 k]  18432 B
#define XL_OFF 18432          // X lo
#define WH_OFF 36864          // W hi  [64 experts][64 k]   9216 B
#define WL_OFF 46080          // W lo
#define BUF_BYTES 55296
#define SMEM_BYTES (2 * BUF_BYTES)
#define LSTR 132              // logits [64 experts][128 tokens] pitch (words)

__device__ __forceinline__ uint32_t smem_u32(const void* p) {
    uint32_t a;
    asm("{ .reg .u64 t; cvta.to.shared.u64 t, %1; cvt.u32.u64 %0, t; }" : "=r"(a) : "l"(p));
    return a;
}

#define LDSM4(r, addr) \
    asm volatile("ldmatrix.sync.aligned.m8n8.x4.shared.b16 {%0,%1,%2,%3}, [%4];" \
        : "=r"((r)[0]), "=r"((r)[1]), "=r"((r)[2]), "=r"((r)[3]) : "r"(addr))

#define MMA16816(d, a, b0, b1) \
    asm volatile("mma.sync.aligned.m16n8k16.row.col.f32.bf16.bf16.f32 " \
        "{%0,%1,%2,%3},{%4,%5,%6,%7},{%8,%9},{%0,%1,%2,%3};" \
        : "+f"((d)[0]), "+f"((d)[1]), "+f"((d)[2]), "+f"((d)[3]) \
        : "r"((a)[0]), "r"((a)[1]), "r"((a)[2]), "r"((a)[3]), "r"(b0), "r"(b1))

// one split-product term: 8 MMAs, each acc tile touched once (reuse distance 8)
#define MMA_TERM(A0, A1, B0, B1) \
    MMA16816(acc[0][0], A0, (B0)[0], (B0)[1]); \
    MMA16816(acc[0][1], A0, (B0)[2], (B0)[3]); \
    MMA16816(acc[0][2], A0, (B1)[0], (B1)[1]); \
    MMA16816(acc[0][3], A0, (B1)[2], (B1)[3]); \
    MMA16816(acc[1][0], A1, (B0)[0], (B0)[1]); \
    MMA16816(acc[1][1], A1, (B0)[2], (B0)[3]); \
    MMA16816(acc[1][2], A1, (B1)[0], (B1)[1]); \
    MMA16816(acc[1][3], A1, (B1)[2], (B1)[3]);

// Compensated fp32 accumulate: two-prod (FMA) + two-sum, all on the FFMA pipe.
__device__ __forceinline__ void comp_fma(float a, float b, float& s, float& c) {
    float p = a * b;
    float e = fmaf(a, b, -p);
    float t = s + p;
    float bp = t - s;
    float err = (s - (t - bp)) + (p - bp);
    s = t;
    c += err + e;
}

// Exact dot X[tok] . W[e] per warp (compensated fp32, 4 ILP chains).
__device__ __forceinline__ double warp_exact_dot(
    const float* __restrict__ X, const float* __restrict__ W,
    int tok, int e, int lane) {
    const float4* xp = reinterpret_cast<const float4*>(X + (size_t)tok * ND) + lane;
    const float4* wp = reinterpret_cast<const float4*>(W + (size_t)e * ND) + lane;
    float s0 = 0.f, k0 = 0.f, s1 = 0.f, k1 = 0.f;
    float s2 = 0.f, k2 = 0.f, s3 = 0.f, k3 = 0.f;
    #pragma unroll 8
    for (int it = 0; it < 32; it++) {
        float4 a = xp[it * 32];
        float4 b = wp[it * 32];
        comp_fma(a.x, b.x, s0, k0);
        comp_fma(a.y, b.y, s1, k1);
        comp_fma(a.z, b.z, s2, k2);
        comp_fma(a.w, b.w, s3, k3);
    }
    double s = ((double)s0 + s1) + ((double)s2 + s3)
             + (((double)k0 + k1) + ((double)k2 + k3));
    #pragma unroll
    for (int o = 16; o; o >>= 1)
        s += __shfl_xor_sync(0xffffffffu, s, o);
    return s;
}

extern __shared__ char dsm[];

__global__ __launch_bounds__(NTHREADS, 1)
void router_gemm(const float* __restrict__ X, const float* __restrict__ W,
                 float* __restrict__ out) {
    __shared__ float s_max[BM];
    __shared__ float s_invZ[BM];
    __shared__ float s_cnt[NE];
    __shared__ float s_sumP[NE];
    __shared__ int   s_nfix;
    __shared__ short s_ftok[CTAFIX];
    __shared__ uint2 s_fcand[CTAFIX];
    __shared__ short s_fcnt[CTAFIX];
    __shared__ float s_ex[NE];
    __shared__ int   s_last;

    const int tid = threadIdx.x;
    const int lane = tid & 31;
    const int wid = tid >> 5;          // 0..15
    const int kgrp = wid >> 3;         // 0: kk 0-1, 1: kk 2-3
    const int wsub = wid & 7;          // tile warp id (as r10)
    const int warp_m = wsub & 1;       // expert half  (32 experts)
    const int warp_n = wsub >> 1;      // token quarter (32 tokens)
    const int mblk = blockIdx.x * BM;
    const uint32_t smem = smem_u32(dsm);

    if (tid < NE) { s_cnt[tid] = 0.f; s_sumP[tid] = 0.f; }
    if (tid == 0) s_nfix = 0;

    // ---- GMEM load mapping (512 threads): instr l: row = (tid>>4)+32l ----
    const int row0 = tid >> 4;         // 0..31
    const int f4i  = tid & 15;
    const float4* xg = reinterpret_cast<const float4*>(X + (size_t)(mblk + row0) * ND) + f4i;
    const float4* wg = reinterpret_cast<const float4*>(W + (size_t)row0 * ND) + f4i;

    float4 xA[4], wA[2], xB[4], wB[2];

#define LDGX(dst, c) { _Pragma("unroll") for (int l = 0; l < 4; l++) \
        dst[l] = xg[(size_t)l * 32 * (ND / 4) + (c) * 16]; }
#define LDGW(dst, c) { _Pragma("unroll") for (int l = 0; l < 2; l++) \
        dst[l] = wg[(size_t)l * 32 * (ND / 4) + (c) * 16]; }

    // split f32 -> bf16 hi (truncate) + bf16 lo (rn of residual), store both
#define CVTSTS(v, hoff, loff) { \
    uint32_t h0, h1, l0, l1; \
    asm("prmt.b32 %0, %1, %2, 0x7632;" : "=r"(h0) : "r"(__float_as_uint((v).x)), "r"(__float_as_uint((v).y))); \
    asm("prmt.b32 %0, %1, %2, 0x7632;" : "=r"(h1) : "r"(__float_as_uint((v).z)), "r"(__float_as_uint((v).w))); \
    float lx = (v).x - __uint_as_float(__float_as_uint((v).x) & 0xffff0000u); \
    float ly = (v).y - __uint_as_float(__float_as_uint((v).y) & 0xffff0000u); \
    float lz = (v).z - __uint_as_float(__float_as_uint((v).z) & 0xffff0000u); \
    float lw = (v).w - __uint_as_float(__float_as_uint((v).w) & 0xffff0000u); \
    asm("cvt.rn.bf16x2.f32 %0, %1, %2;" : "=r"(l0) : "f"(ly), "f"(lx)); \
    asm("cvt.rn.bf16x2.f32 %0, %1, %2;" : "=r"(l1) : "f"(lw), "f"(lz)); \
    *reinterpret_cast<uint2*>(dsm + (hoff)) = make_uint2(h0, h1); \
    *reinterpret_cast<uint2*>(dsm + (loff)) = make_uint2(l0, l1); }

#define STORE_CHUNK(sx, sw, bufoff) { \
    _Pragma("unroll") for (int l = 0; l < 4; l++) { \
        int boff = (row0 + 32 * l) * XROWB + f4i * 8; \
        CVTSTS(sx[l], (bufoff) + XH_OFF + boff, (bufoff) + XL_OFF + boff); } \
    _Pragma("unroll") for (int l = 0; l < 2; l++) { \
        int boff = (row0 + 32 * l) * XROWB + f4i * 8; \
        CVTSTS(sw[l], (bufoff) + WH_OFF + boff, (bufoff) + WL_OFF + boff); } }

    // ---- fragment addresses (ldmatrix), buffer-invariant parts ----
    uint32_t aH0, aL0, bH0, bL0;
    {
        int ar = warp_m * 32 + (lane & 15);
        int ac = (lane >> 4) * 16;
        aH0 = smem + WH_OFF + ar * XROWB + ac;
        aL0 = smem + WL_OFF + ar * XROWB + ac;
        int br = warp_n * 32 + ((lane >> 4) * 8) + (lane & 7);
        int bc = ((lane >> 3) & 1) * 16;
        bH0 = smem + XH_OFF + br * XROWB + bc;
        bL0 = smem + XL_OFF + br * XROWB + bc;
    }

    float acc[2][4][4];
    #pragma unroll
    for (int s = 0; s < 2; s++)
        #pragma unroll
        for (int j = 0; j < 4; j++)
            #pragma unroll
            for (int q = 0; q < 4; q++) acc[s][j][q] = 0.f;

    // each warp-group handles 2 of the 4 k-sub-steps of every chunk
#define MMA_CHUNK(cb) { \
    _Pragma("unroll") \
    for (int kk2 = 0; kk2 < 2; kk2++) { \
        const uint32_t off = (cb) + (uint32_t)(kgrp * 2 + kk2) * 32; \
        uint32_t ah0[4], ah1[4], al0[4], al1[4]; \
        uint32_t bh0[4], bh1[4], bl0[4], bl1[4]; \
        LDSM4(ah0, aH0 + off);               LDSM4(ah1, aH0 + off + 16 * XROWB); \
        LDSM4(al0, aL0 + off);               LDSM4(al1, aL0 + off + 16 * XROWB); \
        LDSM4(bh0, bH0 + off);               LDSM4(bh1, bH0 + off + 16 * XROWB); \
        LDSM4(bl0, bL0 + off);               LDSM4(bl1, bL0 + off + 16 * XROWB); \
        MMA_TERM(ah0, ah1, bh0, bh1); \
        MMA_TERM(ah0, ah1, bl0, bl1); \
        MMA_TERM(al0, al1, bh0, bh1); \
    } }

    // prologue: distance-2 prefetch pipeline (as r10)
    LDGX(xA, 0); LDGW(wA, 0);
    LDGX(xB, 1); LDGW(wB, 1);
    STORE_CHUNK(xA, wA, 0);
    __syncthreads();

    for (int c = 0; c < NCHUNK; c += 2) {
        if (c + 2 < NCHUNK) { LDGX(xA, c + 2); LDGW(wA, c + 2); }
        MMA_CHUNK(0);                                 // chunk c from buf0
        STORE_CHUNK(xB, wB, BUF_BYTES);               // chunk c+1 -> buf1
        __syncthreads();

        if (c + 3 < NCHUNK) { LDGX(xB, c + 3); LDGW(wB, c + 3); }
        MMA_CHUNK(BUF_BYTES);                         // chunk c+1 from buf1
        if (c + 2 < NCHUNK) { STORE_CHUNK(xA, wA, 0); }  // chunk c+2 -> buf0
        __syncthreads();
    }

    // ---- epilogue: combine warp-group partials into logits[e][t] (buf 0) ----
    float* L = reinterpret_cast<float*>(dsm);
    if (kgrp == 0) {
        #pragma unroll
        for (int s = 0; s < 2; s++) {
            int er = warp_m * 32 + s * 16 + (lane >> 2);
            #pragma unroll
            for (int j = 0; j < 4; j++) {
                int tc = warp_n * 32 + j * 8 + 2 * (lane & 3);
                *reinterpret_cast<float2*>(&L[er * LSTR + tc])       = make_float2(acc[s][j][0], acc[s][j][1]);
                *reinterpret_cast<float2*>(&L[(er + 8) * LSTR + tc]) = make_float2(acc[s][j][2], acc[s][j][3]);
            }
        }
    }
    __syncthreads();
    if (kgrp == 1) {
        #pragma unroll
        for (int s = 0; s < 2; s++) {
            int er = warp_m * 32 + s * 16 + (lane >> 2);
            #pragma unroll
            for (int j = 0; j < 4; j++) {
                int tc = warp_n * 32 + j * 8 + 2 * (lane & 3);
                float2 a0 = *reinterpret_cast<float2*>(&L[er * LSTR + tc]);
                float2 a1 = *reinterpret_cast<float2*>(&L[(er + 8) * LSTR + tc]);
                a0.x += acc[s][j][0]; a0.y += acc[s][j][1];
                a1.x += acc[s][j][2]; a1.y += acc[s][j][3];
                *reinterpret_cast<float2*>(&L[er * LSTR + tc])       = a0;
                *reinterpret_cast<float2*>(&L[(er + 8) * LSTR + tc]) = a1;
            }
        }
    }
    __syncthreads();

    // pass 1: per-token top-2, routing softmax, candidate collection
    if (tid < BM) {
        const int t = tid;
        const float NEG = __int_as_float(0xff800000);
        float best = NEG, sec = NEG;
        int bi = 0, si = 0;
        #pragma unroll 8
        for (int e = 0; e < NE; e++) {
            float v = L[e * LSTR + t];
            if (v > best)      { sec = best; si = bi; best = v; bi = e; }
            else if (v > sec)  { sec = v; si = e; }
        }
        float Z = 0.f;
        uint32_t c0 = 0, c1 = 0;
        int cnt = 0;
        const float thresh = sec - TAU;
        #pragma unroll 8
        for (int e = 0; e < NE; e++) {
            float v = L[e * LSTR + t];
            Z += __expf(v - best);
            if (v > thresh) {
                if (cnt < 4)      c0 |= (uint32_t)e << (8 * cnt);
                else if (cnt < 8) c1 |= (uint32_t)e << (8 * (cnt - 4));
                cnt++;
            }
        }

        float w0 = 1.f / (1.f + __expf(sec - best));
        float w1 = 1.f - w0;

        size_t tok = (size_t)(mblk + t);
        out[tok * 2 + 0] = w0;
        out[tok * 2 + 1] = w1;
        out[(size_t)2 * NT + tok * 2 + 0] = (float)bi;
        out[(size_t)2 * NT + tok * 2 + 1] = (float)si;

        s_max[t]  = best;
        s_invZ[t] = 1.f / Z;
        atomicAdd(&s_cnt[bi], 1.f);
        atomicAdd(&s_cnt[si], 1.f);

        if (cnt > 2 || (best - sec) < TAU) {
            int idx = atomicAdd(&s_nfix, 1);
            s_ftok[idx]  = (short)t;
            s_fcand[idx] = make_uint2(c0, c1);
            s_fcnt[idx]  = (short)cnt;
        }
    }
    __syncthreads();

    // pass 2: per-expert softmax-prob sums for aux loss (8 token groups of 16)
    {
        const int e = tid & 63;
        const int q = tid >> 6;
        float ssum = 0.f;
        #pragma unroll 8
        for (int t = q * 16; t < q * 16 + 16; t++)
            ssum += __expf(L[e * LSTR + t] - s_max[t]) * s_invZ[t];
        atomicAdd(&s_sumP[e], ssum);
    }
    __syncthreads();

    if (tid < NE) {
        atomicAdd(&g_sumP[tid], s_sumP[tid]);
        atomicAdd(&g_cnt[tid],  s_cnt[tid]);
    }

    // ---- inline exact fixup of this CTA's flagged tokens ----
    const int nfix = s_nfix;
    for (int i = 0; i < nfix; i++) {
        const int tok = mblk + (int)s_ftok[i];
        const int cnt = (int)s_fcnt[i];
        const uint2 cd = s_fcand[i];

        if (cnt <= 8) {
            // one warp per candidate expert (parallel)
            if (wid < cnt) {
                int e = (int)((wid < 4 ? (cd.x >> (8 * wid))
                                       : (cd.y >> (8 * (wid - 4)))) & 0xffu);
                double s = warp_exact_dot(X, W, tok, e, lane);
                if (lane == 0) s_ex[wid] = (float)s;
            }
            __syncthreads();
            if (tid == 0) {
                float best = -1e30f, sec = -1e30f;
                int bi = 0, si = 0;
                for (int j = 0; j < cnt; j++) {
                    int e = (int)((j < 4 ? (cd.x >> (8 * j))
                                         : (cd.y >> (8 * (j - 4)))) & 0xffu);
                    float v = s_ex[j];
                    if (v > best)     { sec = best; si = bi; best = v; bi = e; }
                    else if (v > sec) { sec = v; si = e; }
                }
                float w0 = 1.f / (1.f + __expf(sec - best));
                out[(size_t)tok * 2 + 0] = w0;
                out[(size_t)tok * 2 + 1] = 1.f - w0;
                out[(size_t)2 * NT + (size_t)tok * 2 + 0] = (float)bi;
                out[(size_t)2 * NT + (size_t)tok * 2 + 1] = (float)si;
            }
            __syncthreads();
        } else {
            // fallback: all 64 experts, 4 per warp (16 warps)
            #pragma unroll 1
            for (int j = 0; j < 4; j++) {
                int e = wid * 4 + j;
                double s = warp_exact_dot(X, W, tok, e, lane);
                if (lane == 0) s_ex[e] = (float)s;
            }
            __syncthreads();
            if (tid == 0) {
                float best = -1e30f, sec = -1e30f;
                int bi = 0, si = 0;
                for (int e = 0; e < NE; e++) {
                    float v = s_ex[e];
                    if (v > best)     { sec = best; si = bi; best = v; bi = e; }
                    else if (v > sec) { sec = v; si = e; }
                }
                float w0 = 1.f / (1.f + __expf(sec - best));
                out[(size_t)tok * 2 + 0] = w0;
                out[(size_t)tok * 2 + 1] = 1.f - w0;
                out[(size_t)2 * NT + (size_t)tok * 2 + 0] = (float)bi;
                out[(size_t)2 * NT + (size_t)tok * 2 + 1] = (float)si;
            }
            __syncthreads();
        }
    }

    // ---- last CTA to finish: aux-loss finalize + scratch re-zero ----
    __threadfence();
    if (tid == 0)
        s_last = (atomicAdd(&g_done, 1) == (int)gridDim.x - 1) ? 1 : 0;
    __syncthreads();
    if (s_last) {
        if (tid < 32) {
            float v = g_cnt[tid] * g_sumP[tid] + g_cnt[tid + 32] * g_sumP[tid + 32];
            #pragma unroll
            for (int o = 16; o; o >>= 1) v += __shfl_xor_sync(0xffffffffu, v, o);
            if (tid == 0)
                out[(size_t)4 * NT] = v * (float)NE / ((float)NT * 2.0f * (float)NT);
        }
        __syncthreads();
        if (tid < NE) { g_sumP[tid] = 0.f; g_cnt[tid] = 0.f; }
        if (tid == 0) g_done = 0;
    }
}

extern "C" void kernel_launch(void* const* d_in, const int* in_sizes, int n_in,
                              void* d_out, int out_size) {
    const float* X = (const float*)d_in[0];   // hidden_states [16384, 4096]
    const float* W = (const float*)d_in[1];   // W_gate        [64, 4096]
    float* out = (float*)d_out;

    cudaFuncSetAttribute(router_gemm, cudaFuncAttributeMaxDynamicSharedMemorySize,
                         SMEM_BYTES);

    router_gemm<<<NT / BM, NTHREADS, SMEM_BYTES>>>(X, W, out);
}

// round 16
// speedup vs baseline: 1.9421x; 1.0996x over previous
#include <cuda_runtime.h>
#include <cstdint>

#define NT 16384
#define ND 4096
#define NE 64
#define BM 128
#define KC 64
#define NCHUNK (ND / KC)
#define NTHREADS 256
#define TAU 2e-3f
#define CTAFIX 128

// ---------------- global scratch (no cudaMalloc; zero-initialized at load,
// re-zeroed by the last CTA each call -> deterministic across graph replays)
__device__ float g_sumP[NE];
__device__ float g_cnt[NE];
__device__ int   g_done;

// ---------------- smem layout: two chunk buffers, each 46080 B ----------------
// fp16 tiles, row pitch 144 B (64 f16 = 128 B + 16 B pad -> conflict-free LDSM)
// X split hi+lo (fp16 residual); W single fp16 rn. Dropped x*w_lo term has
// logit error std ~2.8e-4 (4x below the bf16 variant that failed at 1.07e-3);
// ranking protected by TAU=5-sigma exact fixup.
#define XROWB 144
#define XH_OFF 0              // X hi  [128 tokens][64 k]  18432 B
#define XL_OFF 18432          // X lo
#define WH_OFF 36864          // W     [64 experts][64 k]   9216 B
#define BUF_BYTES 46080
#define SMEM_BYTES (2 * BUF_BYTES)
#define LSTR 132              // logits [64 experts][128 tokens] pitch (words)

__device__ __forceinline__ uint32_t smem_u32(const void* p) {
    uint32_t a;
    asm("{ .reg .u64 t; cvta.to.shared.u64 t, %1; cvt.u32.u64 %0, t; }" : "=r"(a) : "l"(p));
    return a;
}

#define LDSM4(r, addr) \
    asm volatile("ldmatrix.sync.aligned.m8n8.x4.shared.b16 {%0,%1,%2,%3}, [%4];" \
        : "=r"((r)[0]), "=r"((r)[1]), "=r"((r)[2]), "=r"((r)[3]) : "r"(addr))

#define MMA16816(d, a, b0, b1) \
    asm volatile("mma.sync.aligned.m16n8k16.row.col.f32.f16.f16.f32 " \
        "{%0,%1,%2,%3},{%4,%5,%6,%7},{%8,%9},{%0,%1,%2,%3};" \
        : "+f"((d)[0]), "+f"((d)[1]), "+f"((d)[2]), "+f"((d)[3]) \
        : "r"((a)[0]), "r"((a)[1]), "r"((a)[2]), "r"((a)[3]), "r"(b0), "r"(b1))

// one split-product term: 8 MMAs, each acc tile touched once (reuse distance 8)
#define MMA_TERM(A0, A1, B0, B1) \
    MMA16816(acc[0][0], A0, (B0)[0], (B0)[1]); \
    MMA16816(acc[0][1], A0, (B0)[2], (B0)[3]); \
    MMA16816(acc[0][2], A0, (B1)[0], (B1)[1]); \
    MMA16816(acc[0][3], A0, (B1)[2], (B1)[3]); \
    MMA16816(acc[1][0], A1, (B0)[0], (B0)[1]); \
    MMA16816(acc[1][1], A1, (B0)[2], (B0)[3]); \
    MMA16816(acc[1][2], A1, (B1)[0], (B1)[1]); \
    MMA16816(acc[1][3], A1, (B1)[2], (B1)[3]);

// Compensated fp32 accumulate: two-prod (FMA) + two-sum, all on the FFMA pipe.
__device__ __forceinline__ void comp_fma(float a, float b, float& s, float& c) {
    float p = a * b;
    float e = fmaf(a, b, -p);
    float t = s + p;
    float bp = t - s;
    float err = (s - (t - bp)) + (p - bp);
    s = t;
    c += err + e;
}

// Exact dot X[tok] . W[e] per warp (compensated fp32, 4 ILP chains).
__device__ __forceinline__ double warp_exact_dot(
    const float* __restrict__ X, const float* __restrict__ W,
    int tok, int e, int lane) {
    const float4* xp = reinterpret_cast<const float4*>(X + (size_t)tok * ND) + lane;
    const float4* wp = reinterpret_cast<const float4*>(W + (size_t)e * ND) + lane;
    float s0 = 0.f, k0 = 0.f, s1 = 0.f, k1 = 0.f;
    float s2 = 0.f, k2 = 0.f, s3 = 0.f, k3 = 0.f;
    #pragma unroll 8
    for (int it = 0; it < 32; it++) {
        float4 a = xp[it * 32];
        float4 b = wp[it * 32];
        comp_fma(a.x, b.x, s0, k0);
        comp_fma(a.y, b.y, s1, k1);
        comp_fma(a.z, b.z, s2, k2);
        comp_fma(a.w, b.w, s3, k3);
    }
    double s = ((double)s0 + s1) + ((double)s2 + s3)
             + (((double)k0 + k1) + ((double)k2 + k3));
    #pragma unroll
    for (int o = 16; o; o >>= 1)
        s += __shfl_xor_sync(0xffffffffu, s, o);
    return s;
}

extern __shared__ char dsm[];

__global__ __launch_bounds__(NTHREADS, 1)
void router_gemm(const float* __restrict__ X, const float* __restrict__ W,
                 float* __restrict__ out) {
    __shared__ float s_max[BM];
    __shared__ float s_invZ[BM];
    __shared__ float s_cnt[NE];
    __shared__ float s_sumP[NE];
    __shared__ int   s_nfix;
    __shared__ short s_ftok[CTAFIX];
    __shared__ uint2 s_fcand[CTAFIX];
    __shared__ short s_fcnt[CTAFIX];
    __shared__ float s_ex[NE];
    __shared__ int   s_last;

    const int tid = threadIdx.x;
    const int lane = tid & 31;
    const int wid = tid >> 5;
    const int warp_m = wid & 1;       // expert half  (32 experts)
    const int warp_n = wid >> 1;      // token quarter (32 tokens)
    const int mblk = blockIdx.x * BM;
    const uint32_t smem = smem_u32(dsm);

    if (tid < NE) { s_cnt[tid] = 0.f; s_sumP[tid] = 0.f; }
    if (tid == 0) s_nfix = 0;

    // ---- GMEM load mapping: instr l: row = (tid>>4)+16l, f4 = tid&15 ----
    const int row0 = tid >> 4;
    const int f4i  = tid & 15;
    const float4* xg = reinterpret_cast<const float4*>(X + (size_t)(mblk + row0) * ND) + f4i;
    const float4* wg = reinterpret_cast<const float4*>(W + (size_t)row0 * ND) + f4i;

    float4 xA[8], wA[4], xB[8], wB[4];

#define LDGX(dst, c) { _Pragma("unroll") for (int l = 0; l < 8; l++) \
        dst[l] = xg[(size_t)l * 16 * (ND / 4) + (c) * 16]; }
#define LDGW(dst, c) { _Pragma("unroll") for (int l = 0; l < 4; l++) \
        dst[l] = wg[(size_t)l * 16 * (ND / 4) + (c) * 16]; }

    // X: split f32 -> f16 hi (rn) + f16 lo (rn of residual), store both
#define CVTSTS(v, hoff, loff) { \
    uint32_t h0, h1, l0, l1; \
    asm("cvt.rn.f16x2.f32 %0, %1, %2;" : "=r"(h0) : "f"((v).y), "f"((v).x)); \
    asm("cvt.rn.f16x2.f32 %0, %1, %2;" : "=r"(h1) : "f"((v).w), "f"((v).z)); \
    float bx, by, bz, bw; \
    asm("{ .reg .f16 l, h; mov.b32 {l, h}, %2; cvt.f32.f16 %0, l; cvt.f32.f16 %1, h; }" \
        : "=f"(bx), "=f"(by) : "r"(h0)); \
    asm("{ .reg .f16 l, h; mov.b32 {l, h}, %2; cvt.f32.f16 %0, l; cvt.f32.f16 %1, h; }" \
        : "=f"(bz), "=f"(bw) : "r"(h1)); \
    float lx = (v).x - bx, ly = (v).y - by, lz = (v).z - bz, lw = (v).w - bw; \
    asm("cvt.rn.f16x2.f32 %0, %1, %2;" : "=r"(l0) : "f"(ly), "f"(lx)); \
    asm("cvt.rn.f16x2.f32 %0, %1, %2;" : "=r"(l1) : "f"(lw), "f"(lz)); \
    *reinterpret_cast<uint2*>(dsm + (hoff)) = make_uint2(h0, h1); \
    *reinterpret_cast<uint2*>(dsm + (loff)) = make_uint2(l0, l1); }

    // W: single f16 rn
#define CVTSTS_HI(v, hoff) { \
    uint32_t h0, h1; \
    asm("cvt.rn.f16x2.f32 %0, %1, %2;" : "=r"(h0) : "f"((v).y), "f"((v).x)); \
    asm("cvt.rn.f16x2.f32 %0, %1, %2;" : "=r"(h1) : "f"((v).w), "f"((v).z)); \
    *reinterpret_cast<uint2*>(dsm + (hoff)) = make_uint2(h0, h1); }

#define STORE_CHUNK(sx, sw, bufoff) { \
    _Pragma("unroll") for (int l = 0; l < 8; l++) { \
        int boff = (row0 + 16 * l) * XROWB + f4i * 8; \
        CVTSTS(sx[l], (bufoff) + XH_OFF + boff, (bufoff) + XL_OFF + boff); } \
    _Pragma("unroll") for (int l = 0; l < 4; l++) { \
        int boff = (row0 + 16 * l) * XROWB + f4i * 8; \
        CVTSTS_HI(sw[l], (bufoff) + WH_OFF + boff); } }

    // ---- fragment addresses (ldmatrix), buffer-invariant parts ----
    uint32_t aH0, bH0, bL0;
    {
        int ar = warp_m * 32 + (lane & 15);
        int ac = (lane >> 4) * 16;
        aH0 = smem + WH_OFF + ar * XROWB + ac;
        int br = warp_n * 32 + ((lane >> 4) * 8) + (lane & 7);
        int bc = ((lane >> 3) & 1) * 16;
        bH0 = smem + XH_OFF + br * XROWB + bc;
        bL0 = smem + XL_OFF + br * XROWB + bc;
    }

    float acc[2][4][4];
    #pragma unroll
    for (int s = 0; s < 2; s++)
        #pragma unroll
        for (int j = 0; j < 4; j++)
            #pragma unroll
            for (int q = 0; q < 4; q++) acc[s][j][q] = 0.f;

#define MMA_CHUNK(cb) { \
    _Pragma("unroll") \
    for (int kk = 0; kk < 4; kk++) { \
        const uint32_t off = (cb) + kk * 32; \
        uint32_t ah0[4], ah1[4]; \
        uint32_t bh0[4], bh1[4], bl0[4], bl1[4]; \
        LDSM4(ah0, aH0 + off);               LDSM4(ah1, aH0 + off + 16 * XROWB); \
        LDSM4(bh0, bH0 + off);               LDSM4(bh1, bH0 + off + 16 * XROWB); \
        LDSM4(bl0, bL0 + off);               LDSM4(bl1, bL0 + off + 16 * XROWB); \
        MMA_TERM(ah0, ah1, bh0, bh1); \
        MMA_TERM(ah0, ah1, bl0, bl1); \
    } }

    // prologue: distance-2 prefetch pipeline
    LDGX(xA, 0); LDGW(wA, 0);
    LDGX(xB, 1); LDGW(wB, 1);
    STORE_CHUNK(xA, wA, 0);
    __syncthreads();

    for (int c = 0; c < NCHUNK; c += 2) {
        if (c + 2 < NCHUNK) { LDGX(xA, c + 2); LDGW(wA, c + 2); }
        MMA_CHUNK(0);                                 // chunk c from buf0
        STORE_CHUNK(xB, wB, BUF_BYTES);               // chunk c+1 -> buf1
        __syncthreads();

        if (c + 3 < NCHUNK) { LDGX(xB, c + 3); LDGW(wB, c + 3); }
        MMA_CHUNK(BUF_BYTES);                         // chunk c+1 from buf1
        if (c + 2 < NCHUNK) { STORE_CHUNK(xA, wA, 0); }  // chunk c+2 -> buf0
        __syncthreads();
    }

    // ---- epilogue: fragments -> logits[e][t] in smem buffer 0 ----
    float* L = reinterpret_cast<float*>(dsm);
    #pragma unroll
    for (int s = 0; s < 2; s++) {
        int er = warp_m * 32 + s * 16 + (lane >> 2);
        #pragma unroll
        for (int j = 0; j < 4; j++) {
            int tc = warp_n * 32 + j * 8 + 2 * (lane & 3);
            *reinterpret_cast<float2*>(&L[er * LSTR + tc])       = make_float2(acc[s][j][0], acc[s][j][1]);
            *reinterpret_cast<float2*>(&L[(er + 8) * LSTR + tc]) = make_float2(acc[s][j][2], acc[s][j][3]);
        }
    }
    __syncthreads();

    // pass 1: per-token top-2, routing softmax, candidate collection
    if (tid < BM) {
        const int t = tid;
        const float NEG = __int_as_float(0xff800000);
        float best = NEG, sec = NEG;
        int bi = 0, si = 0;
        #pragma unroll 8
        for (int e = 0; e < NE; e++) {
            float v = L[e * LSTR + t];
            if (v > best)      { sec = best; si = bi; best = v; bi = e; }
            else if (v > sec)  { sec = v; si = e; }
        }
        float Z = 0.f;
        uint32_t c0 = 0, c1 = 0;
        int cnt = 0;
        const float thresh = sec - TAU;
        #pragma unroll 8
        for (int e = 0; e < NE; e++) {
            float v = L[e * LSTR + t];
            Z += __expf(v - best);
            if (v > thresh) {
                if (cnt < 4)      c0 |= (uint32_t)e << (8 * cnt);
                else if (cnt < 8) c1 |= (uint32_t)e << (8 * (cnt - 4));
                cnt++;
            }
        }

        float w0 = 1.f / (1.f + __expf(sec - best));
        float w1 = 1.f - w0;

        size_t tok = (size_t)(mblk + t);
        out[tok * 2 + 0] = w0;
        out[tok * 2 + 1] = w1;
        out[(size_t)2 * NT + tok * 2 + 0] = (float)bi;
        out[(size_t)2 * NT + tok * 2 + 1] = (float)si;

        s_max[t]  = best;
        s_invZ[t] = 1.f / Z;
        atomicAdd(&s_cnt[bi], 1.f);
        atomicAdd(&s_cnt[si], 1.f);

        if (cnt > 2 || (best - sec) < TAU) {
            int idx = atomicAdd(&s_nfix, 1);
            s_ftok[idx]  = (short)t;
            s_fcand[idx] = make_uint2(c0, c1);
            s_fcnt[idx]  = (short)cnt;
        }
    }
    __syncthreads();

    // pass 2: per-expert softmax-prob sums for aux loss
    {
        const int e = tid & 63;
        const int q = tid >> 6;
        float ssum = 0.f;
        #pragma unroll 8
        for (int t = q * 32; t < q * 32 + 32; t++)
            ssum += __expf(L[e * LSTR + t] - s_max[t]) * s_invZ[t];
        atomicAdd(&s_sumP[e], ssum);
    }
    __syncthreads();

    if (tid < NE) {
        atomicAdd(&g_sumP[tid], s_sumP[tid]);
        atomicAdd(&g_cnt[tid],  s_cnt[tid]);
    }

    // ---- inline exact fixup of this CTA's flagged tokens ----
    const int nfix = s_nfix;
    for (int i = 0; i < nfix; i++) {
        const int tok = mblk + (int)s_ftok[i];
        const int cnt = (int)s_fcnt[i];
        const uint2 cd = s_fcand[i];

        if (cnt <= 8) {
            // one warp per candidate expert (parallel)
            if (wid < cnt) {
                int e = (int)((wid < 4 ? (cd.x >> (8 * wid))
                                       : (cd.y >> (8 * (wid - 4)))) & 0xffu);
                double s = warp_exact_dot(X, W, tok, e, lane);
                if (lane == 0) s_ex[wid] = (float)s;
            }
            __syncthreads();
            if (tid == 0) {
                float best = -1e30f, sec = -1e30f;
                int bi = 0, si = 0;
                for (int j = 0; j < cnt; j++) {
                    int e = (int)((j < 4 ? (cd.x >> (8 * j))
                                         : (cd.y >> (8 * (j - 4)))) & 0xffu);
                    float v = s_ex[j];
                    if (v > best)     { sec = best; si = bi; best = v; bi = e; }
                    else if (v > sec) { sec = v; si = e; }
                }
                float w0 = 1.f / (1.f + __expf(sec - best));
                out[(size_t)tok * 2 + 0] = w0;
                out[(size_t)tok * 2 + 1] = 1.f - w0;
                out[(size_t)2 * NT + (size_t)tok * 2 + 0] = (float)bi;
                out[(size_t)2 * NT + (size_t)tok * 2 + 1] = (float)si;
            }
            __syncthreads();
        } else {
            // fallback: all 64 experts, 8 per warp
            #pragma unroll 1
            for (int j = 0; j < 8; j++) {
                int e = wid * 8 + j;
                double s = warp_exact_dot(X, W, tok, e, lane);
                if (lane == 0) s_ex[e] = (float)s;
            }
            __syncthreads();
            if (tid == 0) {
                float best = -1e30f, sec = -1e30f;
                int bi = 0, si = 0;
                for (int e = 0; e < NE; e++) {
                    float v = s_ex[e];
                    if (v > best)     { sec = best; si = bi; best = v; bi = e; }
                    else if (v > sec) { sec = v; si = e; }
                }
                float w0 = 1.f / (1.f + __expf(sec - best));
                out[(size_t)tok * 2 + 0] = w0;
                out[(size_t)tok * 2 + 1] = 1.f - w0;
                out[(size_t)2 * NT + (size_t)tok * 2 + 0] = (float)bi;
                out[(size_t)2 * NT + (size_t)tok * 2 + 1] = (float)si;
            }
            __syncthreads();
        }
    }

    // ---- last CTA to finish: aux-loss finalize + scratch re-zero ----
    __threadfence();
    if (tid == 0)
        s_last = (atomicAdd(&g_done, 1) == (int)gridDim.x - 1) ? 1 : 0;
    __syncthreads();
    if (s_last) {
        if (tid < 32) {
            float v = g_cnt[tid] * g_sumP[tid] + g_cnt[tid + 32] * g_sumP[tid + 32];
            #pragma unroll
            for (int o = 16; o; o >>= 1) v += __shfl_xor_sync(0xffffffffu, v, o);
            if (tid == 0)
                out[(size_t)4 * NT] = v * (float)NE / ((float)NT * 2.0f * (float)NT);
        }
        __syncthreads();
        if (tid < NE) { g_sumP[tid] = 0.f; g_cnt[tid] = 0.f; }
        if (tid == 0) g_done = 0;
    }
}

extern "C" void kernel_launch(void* const* d_in, const int* in_sizes, int n_in,
                              void* d_out, int out_size) {
    const float* X = (const float*)d_in[0];   // hidden_states [16384, 4096]
    const float* W = (const float*)d_in[1];   // W_gate        [64, 4096]
    float* out = (float*)d_out;

    cudaFuncSetAttribute(router_gemm, cudaFuncAttributeMaxDynamicSharedMemorySize,
                         SMEM_BYTES);

    router_gemm<<<NT / BM, NTHREADS, SMEM_BYTES>>>(X, W, out);
}

// round 17
// speedup vs baseline: 2.2488x; 1.1579x over previous
#include <cuda_runtime.h>
#include <cstdint>

#define NT 16384
#define ND 4096
#define NE 64
#define BM 128
#define KC 64
#define NCHUNK (ND / KC)
#define NTHREADS 256
#define TAU 3e-3f
#define CTAFIX 128

// ---------------- global scratch (no cudaMalloc; zero-initialized at load,
// re-zeroed by the last CTA each call -> deterministic across graph replays)
__device__ float g_sumP[NE];
__device__ float g_cnt[NE];
__device__ int   g_done;

// ---------------- smem layout: two chunk buffers, each 27648 B ----------------
// fp16 tiles, row pitch 144 B (64 f16 = 128 B + 16 B pad -> conflict-free LDSM)
// Single-term pure-fp16 GEMM: logit error std ~4e-4 (r16 measured 1.35e-4 from
// W-side alone; X-side adds the symmetric amount). Ranking exact via TAU=5sigma
// compensated-fp32 fixup.
#define XROWB 144
#define XH_OFF 0              // X  [128 tokens][64 k]  18432 B
#define WH_OFF 18432          // W  [64 experts][64 k]   9216 B
#define BUF_BYTES 27648
#define SMEM_BYTES (2 * BUF_BYTES)
#define LSTR 132              // logits [64 experts][128 tokens] pitch (words)

__device__ __forceinline__ uint32_t smem_u32(const void* p) {
    uint32_t a;
    asm("{ .reg .u64 t; cvta.to.shared.u64 t, %1; cvt.u32.u64 %0, t; }" : "=r"(a) : "l"(p));
    return a;
}

#define LDSM4(r, addr) \
    asm volatile("ldmatrix.sync.aligned.m8n8.x4.shared.b16 {%0,%1,%2,%3}, [%4];" \
        : "=r"((r)[0]), "=r"((r)[1]), "=r"((r)[2]), "=r"((r)[3]) : "r"(addr))

#define MMA16816(d, a, b0, b1) \
    asm volatile("mma.sync.aligned.m16n8k16.row.col.f32.f16.f16.f32 " \
        "{%0,%1,%2,%3},{%4,%5,%6,%7},{%8,%9},{%0,%1,%2,%3};" \
        : "+f"((d)[0]), "+f"((d)[1]), "+f"((d)[2]), "+f"((d)[3]) \
        : "r"((a)[0]), "r"((a)[1]), "r"((a)[2]), "r"((a)[3]), "r"(b0), "r"(b1))

// 8 MMAs, each acc tile touched once (reuse distance 8)
#define MMA_TERM(A0, A1, B0, B1) \
    MMA16816(acc[0][0], A0, (B0)[0], (B0)[1]); \
    MMA16816(acc[0][1], A0, (B0)[2], (B0)[3]); \
    MMA16816(acc[0][2], A0, (B1)[0], (B1)[1]); \
    MMA16816(acc[0][3], A0, (B1)[2], (B1)[3]); \
    MMA16816(acc[1][0], A1, (B0)[0], (B0)[1]); \
    MMA16816(acc[1][1], A1, (B0)[2], (B0)[3]); \
    MMA16816(acc[1][2], A1, (B1)[0], (B1)[1]); \
    MMA16816(acc[1][3], A1, (B1)[2], (B1)[3]);

// Compensated fp32 accumulate: two-prod (FMA) + two-sum, all on the FFMA pipe.
__device__ __forceinline__ void comp_fma(float a, float b, float& s, float& c) {
    float p = a * b;
    float e = fmaf(a, b, -p);
    float t = s + p;
    float bp = t - s;
    float err = (s - (t - bp)) + (p - bp);
    s = t;
    c += err + e;
}

// Exact dot X[tok] . W[e] per warp (compensated fp32, 4 ILP chains).
__device__ __forceinline__ double warp_exact_dot(
    const float* __restrict__ X, const float* __restrict__ W,
    int tok, int e, int lane) {
    const float4* xp = reinterpret_cast<const float4*>(X + (size_t)tok * ND) + lane;
    const float4* wp = reinterpret_cast<const float4*>(W + (size_t)e * ND) + lane;
    float s0 = 0.f, k0 = 0.f, s1 = 0.f, k1 = 0.f;
    float s2 = 0.f, k2 = 0.f, s3 = 0.f, k3 = 0.f;
    #pragma unroll 8
    for (int it = 0; it < 32; it++) {
        float4 a = xp[it * 32];
        float4 b = wp[it * 32];
        comp_fma(a.x, b.x, s0, k0);
        comp_fma(a.y, b.y, s1, k1);
        comp_fma(a.z, b.z, s2, k2);
        comp_fma(a.w, b.w, s3, k3);
    }
    double s = ((double)s0 + s1) + ((double)s2 + s3)
             + (((double)k0 + k1) + ((double)k2 + k3));
    #pragma unroll
    for (int o = 16; o; o >>= 1)
        s += __shfl_xor_sync(0xffffffffu, s, o);
    return s;
}

extern __shared__ char dsm[];

__global__ __launch_bounds__(NTHREADS, 1)
void router_gemm(const float* __restrict__ X, const float* __restrict__ W,
                 float* __restrict__ out) {
    __shared__ float s_max[BM];
    __shared__ float s_invZ[BM];
    __shared__ float s_cnt[NE];
    __shared__ float s_sumP[NE];
    __shared__ int   s_nfix;
    __shared__ short s_ftok[CTAFIX];
    __shared__ uint2 s_fcand[CTAFIX];
    __shared__ short s_fcnt[CTAFIX];
    __shared__ float s_ex[NE];
    __shared__ int   s_last;

    const int tid = threadIdx.x;
    const int lane = tid & 31;
    const int wid = tid >> 5;
    const int warp_m = wid & 1;       // expert half  (32 experts)
    const int warp_n = wid >> 1;      // token quarter (32 tokens)
    const int mblk = blockIdx.x * BM;
    const uint32_t smem = smem_u32(dsm);

    if (tid < NE) { s_cnt[tid] = 0.f; s_sumP[tid] = 0.f; }
    if (tid == 0) s_nfix = 0;

    // ---- GMEM load mapping: instr l: row = (tid>>4)+16l, f4 = tid&15 ----
    const int row0 = tid >> 4;
    const int f4i  = tid & 15;
    const float4* xg = reinterpret_cast<const float4*>(X + (size_t)(mblk + row0) * ND) + f4i;
    const float4* wg = reinterpret_cast<const float4*>(W + (size_t)row0 * ND) + f4i;

    float4 xA[8], wA[4], xB[8], wB[4];

#define LDGX(dst, c) { _Pragma("unroll") for (int l = 0; l < 8; l++) \
        dst[l] = xg[(size_t)l * 16 * (ND / 4) + (c) * 16]; }
#define LDGW(dst, c) { _Pragma("unroll") for (int l = 0; l < 4; l++) \
        dst[l] = wg[(size_t)l * 16 * (ND / 4) + (c) * 16]; }

    // f32 -> f16 rn, packed pair stores
#define CVTSTS_HI(v, hoff) { \
    uint32_t h0, h1; \
    asm("cvt.rn.f16x2.f32 %0, %1, %2;" : "=r"(h0) : "f"((v).y), "f"((v).x)); \
    asm("cvt.rn.f16x2.f32 %0, %1, %2;" : "=r"(h1) : "f"((v).w), "f"((v).z)); \
    *reinterpret_cast<uint2*>(dsm + (hoff)) = make_uint2(h0, h1); }

#define STORE_CHUNK(sx, sw, bufoff) { \
    _Pragma("unroll") for (int l = 0; l < 8; l++) { \
        int boff = (row0 + 16 * l) * XROWB + f4i * 8; \
        CVTSTS_HI(sx[l], (bufoff) + XH_OFF + boff); } \
    _Pragma("unroll") for (int l = 0; l < 4; l++) { \
        int boff = (row0 + 16 * l) * XROWB + f4i * 8; \
        CVTSTS_HI(sw[l], (bufoff) + WH_OFF + boff); } }

    // ---- fragment addresses (ldmatrix), buffer-invariant parts ----
    uint32_t aH0, bH0;
    {
        int ar = warp_m * 32 + (lane & 15);
        int ac = (lane >> 4) * 16;
        aH0 = smem + WH_OFF + ar * XROWB + ac;
        int br = warp_n * 32 + ((lane >> 4) * 8) + (lane & 7);
        int bc = ((lane >> 3) & 1) * 16;
        bH0 = smem + XH_OFF + br * XROWB + bc;
    }

    float acc[2][4][4];
    #pragma unroll
    for (int s = 0; s < 2; s++)
        #pragma unroll
        for (int j = 0; j < 4; j++)
            #pragma unroll
            for (int q = 0; q < 4; q++) acc[s][j][q] = 0.f;

#define MMA_CHUNK(cb) { \
    _Pragma("unroll") \
    for (int kk = 0; kk < 4; kk++) { \
        const uint32_t off = (cb) + kk * 32; \
        uint32_t ah0[4], ah1[4]; \
        uint32_t bh0[4], bh1[4]; \
        LDSM4(ah0, aH0 + off);               LDSM4(ah1, aH0 + off + 16 * XROWB); \
        LDSM4(bh0, bH0 + off);               LDSM4(bh1, bH0 + off + 16 * XROWB); \
        MMA_TERM(ah0, ah1, bh0, bh1); \
    } }

    // prologue: distance-2 prefetch pipeline
    LDGX(xA, 0); LDGW(wA, 0);
    LDGX(xB, 1); LDGW(wB, 1);
    STORE_CHUNK(xA, wA, 0);
    __syncthreads();

    for (int c = 0; c < NCHUNK; c += 2) {
        if (c + 2 < NCHUNK) { LDGX(xA, c + 2); LDGW(wA, c + 2); }
        MMA_CHUNK(0);                                 // chunk c from buf0
        STORE_CHUNK(xB, wB, BUF_BYTES);               // chunk c+1 -> buf1
        __syncthreads();

        if (c + 3 < NCHUNK) { LDGX(xB, c + 3); LDGW(wB, c + 3); }
        MMA_CHUNK(BUF_BYTES);                         // chunk c+1 from buf1
        if (c + 2 < NCHUNK) { STORE_CHUNK(xA, wA, 0); }  // chunk c+2 -> buf0
        __syncthreads();
    }

    // ---- epilogue: fragments -> logits[e][t] in smem buffer 0 ----
    float* L = reinterpret_cast<float*>(dsm);
    #pragma unroll
    for (int s = 0; s < 2; s++) {
        int er = warp_m * 32 + s * 16 + (lane >> 2);
        #pragma unroll
        for (int j = 0; j < 4; j++) {
            int tc = warp_n * 32 + j * 8 + 2 * (lane & 3);
            *reinterpret_cast<float2*>(&L[er * LSTR + tc])       = make_float2(acc[s][j][0], acc[s][j][1]);
            *reinterpret_cast<float2*>(&L[(er + 8) * LSTR + tc]) = make_float2(acc[s][j][2], acc[s][j][3]);
        }
    }
    __syncthreads();

    // pass 1: per-token top-2, routing softmax, candidate collection
    if (tid < BM) {
        const int t = tid;
        const float NEG = __int_as_float(0xff800000);
        float best = NEG, sec = NEG;
        int bi = 0, si = 0;
        #pragma unroll 8
        for (int e = 0; e < NE; e++) {
            float v = L[e * LSTR + t];
            if (v > best)      { sec = best; si = bi; best = v; bi = e; }
            else if (v > sec)  { sec = v; si = e; }
        }
        float Z = 0.f;
        uint32_t c0 = 0, c1 = 0;
        int cnt = 0;
        const float thresh = sec - TAU;
        #pragma unroll 8
        for (int e = 0; e < NE; e++) {
            float v = L[e * LSTR + t];
            Z += __expf(v - best);
            if (v > thresh) {
                if (cnt < 4)      c0 |= (uint32_t)e << (8 * cnt);
                else if (cnt < 8) c1 |= (uint32_t)e << (8 * (cnt - 4));
                cnt++;
            }
        }

        float w0 = 1.f / (1.f + __expf(sec - best));
        float w1 = 1.f - w0;

        size_t tok = (size_t)(mblk + t);
        out[tok * 2 + 0] = w0;
        out[tok * 2 + 1] = w1;
        out[(size_t)2 * NT + tok * 2 + 0] = (float)bi;
        out[(size_t)2 * NT + tok * 2 + 1] = (float)si;

        s_max[t]  = best;
        s_invZ[t] = 1.f / Z;
        atomicAdd(&s_cnt[bi], 1.f);
        atomicAdd(&s_cnt[si], 1.f);

        if (cnt > 2 || (best - sec) < TAU) {
            int idx = atomicAdd(&s_nfix, 1);
            s_ftok[idx]  = (short)t;
            s_fcand[idx] = make_uint2(c0, c1);
            s_fcnt[idx]  = (short)cnt;
        }
    }
    __syncthreads();

    // pass 2: per-expert softmax-prob sums for aux loss
    {
        const int e = tid & 63;
        const int q = tid >> 6;
        float ssum = 0.f;
        #pragma unroll 8
        for (int t = q * 32; t < q * 32 + 32; t++)
            ssum += __expf(L[e * LSTR + t] - s_max[t]) * s_invZ[t];
        atomicAdd(&s_sumP[e], ssum);
    }
    __syncthreads();

    if (tid < NE) {
        atomicAdd(&g_sumP[tid], s_sumP[tid]);
        atomicAdd(&g_cnt[tid],  s_cnt[tid]);
    }

    // ---- inline exact fixup of this CTA's flagged tokens ----
    const int nfix = s_nfix;
    for (int i = 0; i < nfix; i++) {
        const int tok = mblk + (int)s_ftok[i];
        const int cnt = (int)s_fcnt[i];
        const uint2 cd = s_fcand[i];

        if (cnt <= 8) {
            // one warp per candidate expert (parallel)
            if (wid < cnt) {
                int e = (int)((wid < 4 ? (cd.x >> (8 * wid))
                                       : (cd.y >> (8 * (wid - 4)))) & 0xffu);
                double s = warp_exact_dot(X, W, tok, e, lane);
                if (lane == 0) s_ex[wid] = (float)s;
            }
            __syncthreads();
            if (tid == 0) {
                float best = -1e30f, sec = -1e30f;
                int bi = 0, si = 0;
                for (int j = 0; j < cnt; j++) {
                    int e = (int)((j < 4 ? (cd.x >> (8 * j))
                                         : (cd.y >> (8 * (j - 4)))) & 0xffu);
                    float v = s_ex[j];
                    if (v > best)     { sec = best; si = bi; best = v; bi = e; }
                    else if (v > sec) { sec = v; si = e; }
                }
                float w0 = 1.f / (1.f + __expf(sec - best));
                out[(size_t)tok * 2 + 0] = w0;
                out[(size_t)tok * 2 + 1] = 1.f - w0;
                out[(size_t)2 * NT + (size_t)tok * 2 + 0] = (float)bi;
                out[(size_t)2 * NT + (size_t)tok * 2 + 1] = (float)si;
            }
            __syncthreads();
        } else {
            // fallback: all 64 experts, 8 per warp
            #pragma unroll 1
            for (int j = 0; j < 8; j++) {
                int e = wid * 8 + j;
                double s = warp_exact_dot(X, W, tok, e, lane);
                if (lane == 0) s_ex[e] = (float)s;
            }
            __syncthreads();
            if (tid == 0) {
                float best = -1e30f, sec = -1e30f;
                int bi = 0, si = 0;
                for (int e = 0; e < NE; e++) {
                    float v = s_ex[e];
                    if (v > best)     { sec = best; si = bi; best = v; bi = e; }
                    else if (v > sec) { sec = v; si = e; }
                }
                float w0 = 1.f / (1.f + __expf(sec - best));
                out[(size_t)tok * 2 + 0] = w0;
                out[(size_t)tok * 2 + 1] = 1.f - w0;
                out[(size_t)2 * NT + (size_t)tok * 2 + 0] = (float)bi;
                out[(size_t)2 * NT + (size_t)tok * 2 + 1] = (float)si;
            }
            __syncthreads();
        }
    }

    // ---- last CTA to finish: aux-loss finalize + scratch re-zero ----
    __threadfence();
    if (tid == 0)
        s_last = (atomicAdd(&g_done, 1) == (int)gridDim.x - 1) ? 1 : 0;
    __syncthreads();
    if (s_last) {
        if (tid < 32) {
            float v = g_cnt[tid] * g_sumP[tid] + g_cnt[tid + 32] * g_sumP[tid + 32];
            #pragma unroll
            for (int o = 16; o; o >>= 1) v += __shfl_xor_sync(0xffffffffu, v, o);
            if (tid == 0)
                out[(size_t)4 * NT] = v * (float)NE / ((float)NT * 2.0f * (float)NT);
        }
        __syncthreads();
        if (tid < NE) { g_sumP[tid] = 0.f; g_cnt[tid] = 0.f; }
        if (tid == 0) g_done = 0;
    }
}

extern "C" void kernel_launch(void* const* d_in, const int* in_sizes, int n_in,
                              void* d_out, int out_size) {
    const float* X = (const float*)d_in[0];   // hidden_states [16384, 4096]
    const float* W = (const float*)d_in[1];   // W_gate        [64, 4096]
    float* out = (float*)d_out;

    cudaFuncSetAttribute(router_gemm, cudaFuncAttributeMaxDynamicSharedMemorySize,
                         SMEM_BYTES);

    router_gemm<<<NT / BM, NTHREADS, SMEM_BYTES>>>(X, W, out);
}